// round 2
// baseline (speedup 1.0000x reference)
#include <cuda_runtime.h>
#include <math.h>

#define BB 16
#define HH 32
#define KVH 8
#define GG 4
#define DD 128
#define SS 4096
#define NSPLIT 16
#define CHUNK (SS / NSPLIT)   // 256
#define NWARP 8
#define NTHREADS 256

// Scratch for split-KV partials (allocation-free: __device__ globals)
__device__ float g_part[BB * KVH * GG * NSPLIT * DD];   // 16 MB
__device__ float g_m[BB * KVH * GG * NSPLIT];
__device__ float g_l[BB * KVH * GG * NSPLIT];

__global__ __launch_bounds__(NTHREADS, 4)
void attn_partial_kernel(const float* __restrict__ query,
                         const float* __restrict__ k_cache,
                         const float* __restrict__ v_cache,
                         const int* __restrict__ slots,
                         const int* __restrict__ positions,
                         const int* __restrict__ ctx_lens)
{
    const int split = blockIdx.x;
    const int kh    = blockIdx.y;
    const int b     = blockIdx.z;
    const int tid   = threadIdx.x;
    const int warp  = tid >> 5;
    const int lane  = tid & 31;

    const int ctx = ctx_lens[b];

    __shared__ float sh_if[64];            // inv_freq
    __shared__ float sh_qr[GG][DD];        // roped q, 4 heads
    __shared__ int   sh_slot[CHUNK];
    __shared__ int   sh_pos[CHUNK];
    __shared__ float sm_acc[NWARP][GG][DD];
    __shared__ float sm_m[NWARP][GG];
    __shared__ float sm_l[NWARP][GG];

    const int s_base = split * CHUNK;
    const int s_end  = min(s_base + CHUNK, ctx);
    const int n_rows = s_end - s_base;           // may be <= 0

    // Stage slots/positions for this chunk (coalesced)
    if (n_rows > 0) {
        for (int i = tid; i < n_rows; i += NTHREADS) {
            sh_slot[i] = slots[b * SS + s_base + i];
            sh_pos[i]  = positions[b * SS + s_base + i];
        }
    }

    // inv_freq[j] = 10000^(-j/64)
    if (tid < 64) {
        sh_if[tid] = __expf(-(float)tid * (logf(10000.0f) / 64.0f));
    }
    __syncthreads();

    // RoPE the 4 query heads (pos_last), into smem
    const int pos_last = positions[b * SS + (ctx - 1)];
    for (int i = tid; i < GG * 64; i += NTHREADS) {
        int g = i >> 6;
        int j = i & 63;
        float f = sh_if[j];
        float sv, cv;
        sincosf((float)pos_last * f, &sv, &cv);
        const float* qp = query + ((size_t)b * HH + kh * GG + g) * DD;
        float x1 = qp[j];
        float x2 = qp[j + 64];
        sh_qr[g][j]      = x1 * cv - x2 * sv;
        sh_qr[g][j + 64] = x2 * cv + x1 * sv;
    }
    __syncthreads();

    // Each lane owns dim-pairs j0=2*lane, j1=2*lane+1 (and partners +64)
    float qr0[GG], qr1[GG], qr2[GG], qr3[GG];
#pragma unroll
    for (int g = 0; g < GG; g++) {
        qr0[g] = sh_qr[g][2 * lane];
        qr1[g] = sh_qr[g][2 * lane + 1];
        qr2[g] = sh_qr[g][2 * lane + 64];
        qr3[g] = sh_qr[g][2 * lane + 65];
    }
    const float f0 = sh_if[2 * lane];
    const float f1 = sh_if[2 * lane + 1];

    float m[GG], l[GG], acc[GG][4];
#pragma unroll
    for (int g = 0; g < GG; g++) {
        m[g] = -INFINITY;
        l[g] = 0.0f;
        acc[g][0] = acc[g][1] = acc[g][2] = acc[g][3] = 0.0f;
    }

    const float scale = 0.08838834764831845f;  // 1/sqrt(128)

#pragma unroll 2
    for (int i = warp; i < n_rows; i += NWARP) {
        const int slot = sh_slot[i];
        const int pos  = sh_pos[i];

        const float* kp = k_cache + ((size_t)slot * KVH + kh) * DD;
        float2 ka = *(const float2*)(kp + 2 * lane);
        float2 kb = *(const float2*)(kp + 2 * lane + 64);
        const float* vp = v_cache + ((size_t)slot * KVH + kh) * DD;
        float4 v = *(const float4*)(vp + 4 * lane);

        float s0, c0, s1, c1;
        sincosf((float)pos * f0, &s0, &c0);
        sincosf((float)pos * f1, &s1, &c1);

        // RoPE K (pairs (j, j+64))
        float k0 = ka.x * c0 - kb.x * s0;
        float k2 = kb.x * c0 + ka.x * s0;
        float k1 = ka.y * c1 - kb.y * s1;
        float k3 = kb.y * c1 + ka.y * s1;

        float sc[GG];
#pragma unroll
        for (int g = 0; g < GG; g++) {
            float p = qr0[g] * k0 + qr1[g] * k1 + qr2[g] * k2 + qr3[g] * k3;
#pragma unroll
            for (int o = 16; o > 0; o >>= 1)
                p += __shfl_xor_sync(0xffffffffu, p, o);
            sc[g] = p * scale;
        }

#pragma unroll
        for (int g = 0; g < GG; g++) {
            float nm   = fmaxf(m[g], sc[g]);
            float corr = __expf(m[g] - nm);   // exp(-inf - finite) = 0 on first hit
            float p    = __expf(sc[g] - nm);
            m[g] = nm;
            l[g] = l[g] * corr + p;
            acc[g][0] = acc[g][0] * corr + p * v.x;
            acc[g][1] = acc[g][1] * corr + p * v.y;
            acc[g][2] = acc[g][2] * corr + p * v.z;
            acc[g][3] = acc[g][3] * corr + p * v.w;
        }
    }

    // Stash per-warp partials
#pragma unroll
    for (int g = 0; g < GG; g++) {
        if (lane == 0) {
            sm_m[warp][g] = m[g];
            sm_l[warp][g] = l[g];
        }
        sm_acc[warp][g][4 * lane + 0] = acc[g][0];
        sm_acc[warp][g][4 * lane + 1] = acc[g][1];
        sm_acc[warp][g][4 * lane + 2] = acc[g][2];
        sm_acc[warp][g][4 * lane + 3] = acc[g][3];
    }
    __syncthreads();

    // Warps 0..3 combine the 8 warp-partials for head g = warp
    if (warp < GG) {
        const int g = warp;
        float M = -INFINITY;
#pragma unroll
        for (int w = 0; w < NWARP; w++) M = fmaxf(M, sm_m[w][g]);

        float L = 0.0f;
        float o0 = 0.0f, o1 = 0.0f, o2 = 0.0f, o3 = 0.0f;
        if (M > -INFINITY) {
#pragma unroll
            for (int w = 0; w < NWARP; w++) {
                float e = __expf(sm_m[w][g] - M);
                L  += sm_l[w][g] * e;
                o0 += sm_acc[w][g][4 * lane + 0] * e;
                o1 += sm_acc[w][g][4 * lane + 1] * e;
                o2 += sm_acc[w][g][4 * lane + 2] * e;
                o3 += sm_acc[w][g][4 * lane + 3] * e;
            }
        }
        const int idx = (((b * KVH + kh) * GG + g) * NSPLIT + split);
        if (lane == 0) {
            g_m[idx] = M;
            g_l[idx] = L;
        }
        float* op = g_part + (size_t)idx * DD;
        op[4 * lane + 0] = o0;
        op[4 * lane + 1] = o1;
        op[4 * lane + 2] = o2;
        op[4 * lane + 3] = o3;
    }
}

__global__ void attn_combine_kernel(float* __restrict__ out)
{
    const int bhg = blockIdx.x;   // (b*KVH + kh)*GG + g  ==  b*HH + h
    const int d   = threadIdx.x;  // 0..127

    __shared__ float sh_m[NSPLIT], sh_l[NSPLIT];
    if (d < NSPLIT) {
        sh_m[d] = g_m[bhg * NSPLIT + d];
        sh_l[d] = g_l[bhg * NSPLIT + d];
    }
    __syncthreads();

    float M = -INFINITY;
#pragma unroll
    for (int sp = 0; sp < NSPLIT; sp++)
        M = fmaxf(M, sh_m[sp]);

    float L = 0.0f;
    float o = 0.0f;
#pragma unroll
    for (int sp = 0; sp < NSPLIT; sp++) {
        float e = __expf(sh_m[sp] - M);   // 0 for empty splits
        L += sh_l[sp] * e;
        o += g_part[(size_t)(bhg * NSPLIT + sp) * DD + d] * e;
    }
    out[(size_t)bhg * DD + d] = o / L;
}

extern "C" void kernel_launch(void* const* d_in, const int* in_sizes, int n_in,
                              void* d_out, int out_size)
{
    const float* query     = (const float*)d_in[0];
    const float* k_cache   = (const float*)d_in[1];
    const float* v_cache   = (const float*)d_in[2];
    const int*   slots     = (const int*)d_in[3];
    const int*   positions = (const int*)d_in[4];
    const int*   ctx_lens  = (const int*)d_in[5];
    float* out = (float*)d_out;

    dim3 grid(NSPLIT, KVH, BB);
    attn_partial_kernel<<<grid, NTHREADS>>>(query, k_cache, v_cache,
                                            slots, positions, ctx_lens);
    attn_combine_kernel<<<BB * KVH * GG, DD>>>(out);
}

// round 5
// speedup vs baseline: 1.2856x; 1.2856x over previous
#include <cuda_runtime.h>
#include <math.h>

#define BB 16
#define HH 32
#define KVH 8
#define GG 4
#define DD 128
#define SS 4096
#define NSPLIT 16
#define MAXCHUNK 256          // ceil(4096/16)
#define NWARP 8
#define NTHREADS 256
#define POSMAX 4096

// Scratch (allocation-free: __device__ globals)
__device__ float  g_part[BB * KVH * GG * NSPLIT * DD];   // 16 MB
__device__ float  g_m[BB * KVH * GG * NSPLIT];
__device__ float  g_l[BB * KVH * GG * NSPLIT];
__device__ float4 g_tab[POSMAX * 32];                    // 2 MB rope table

// ---------------------------------------------------------------------------
// RoPE table: g_tab[pos*32 + l] = (cos(p f_{2l}), sin(p f_{2l}),
//                                  cos(p f_{2l+1}), sin(p f_{2l+1}))
__global__ void rope_table_kernel()
{
    int idx  = blockIdx.x * blockDim.x + threadIdx.x;   // 0 .. 131071
    int pos  = idx >> 5;
    int l    = idx & 31;
    const float k = logf(10000.0f) / 64.0f;
    float f0 = __expf(-(float)(2 * l) * k);
    float f1 = __expf(-(float)(2 * l + 1) * k);
    float s0, c0, s1, c1;
    sincosf((float)pos * f0, &s0, &c0);
    sincosf((float)pos * f1, &s1, &c1);
    g_tab[idx] = make_float4(c0, s0, c1, s1);
}

// ---------------------------------------------------------------------------
__global__ __launch_bounds__(NTHREADS)
void attn_partial_kernel(const float* __restrict__ query,
                         const float* __restrict__ k_cache,
                         const float* __restrict__ v_cache,
                         const int* __restrict__ slots,
                         const int* __restrict__ positions,
                         const int* __restrict__ ctx_lens)
{
    const int split = blockIdx.x;
    const int kh    = blockIdx.y;
    const int b     = blockIdx.z;
    const int tid   = threadIdx.x;
    const int warp  = tid >> 5;
    const int lane  = tid & 31;

    const int ctx = ctx_lens[b];

    __shared__ float sh_qr[GG][DD];        // roped q, 4 heads
    __shared__ int   sh_slot[MAXCHUNK];
    __shared__ int   sh_pos[MAXCHUNK];
    __shared__ float sm_acc[NWARP][GG][DD];
    __shared__ float sm_m[NWARP][GG];
    __shared__ float sm_l[NWARP][GG];

    // Balanced split: every split of this batch gets ~ctx/16 rows
    const int chunk  = (ctx + NSPLIT - 1) / NSPLIT;
    const int s_base = split * chunk;
    const int n_rows = min(chunk, ctx - s_base);         // may be <= 0

    // Stage slots/positions for this chunk (coalesced)
    for (int i = tid; i < n_rows; i += NTHREADS) {
        sh_slot[i] = slots[b * SS + s_base + i];
        sh_pos[i]  = positions[b * SS + s_base + i];
    }

    // RoPE the 4 query heads at pos_last via the table
    const int pos_last = positions[b * SS + (ctx - 1)];
    for (int i = tid; i < GG * 64; i += NTHREADS) {
        int g = i >> 6;
        int j = i & 63;
        float4 tt = g_tab[pos_last * 32 + (j >> 1)];
        float cv = (j & 1) ? tt.z : tt.x;
        float sv = (j & 1) ? tt.w : tt.y;
        const float* qp = query + ((size_t)b * HH + kh * GG + g) * DD;
        float x1 = qp[j];
        float x2 = qp[j + 64];
        sh_qr[g][j]      = x1 * cv - x2 * sv;
        sh_qr[g][j + 64] = x2 * cv + x1 * sv;
    }
    __syncthreads();

    // Each lane owns dim-pairs (2l, 2l+1) and partners (+64)
    float qr0[GG], qr1[GG], qr2[GG], qr3[GG];
#pragma unroll
    for (int g = 0; g < GG; g++) {
        qr0[g] = sh_qr[g][2 * lane];
        qr1[g] = sh_qr[g][2 * lane + 1];
        qr2[g] = sh_qr[g][2 * lane + 64];
        qr3[g] = sh_qr[g][2 * lane + 65];
    }

    float m[GG], l[GG], acc[GG][4];
#pragma unroll
    for (int g = 0; g < GG; g++) {
        m[g] = -INFINITY;
        l[g] = 0.0f;
        acc[g][0] = acc[g][1] = acc[g][2] = acc[g][3] = 0.0f;
    }

    const float scale = 0.08838834764831845f;  // 1/sqrt(128)

    // ---- 2-deep software pipeline: rows i (bufA) and i+NWARP (bufB) in
    // flight; prefetch i+2*NWARP while computing i.
    float2 kaA, kbA, kaB, kbB;
    float4 vA, tA, vB, tB;

    auto load_row = [&](int row, float2& ka, float2& kb, float4& v, float4& t) {
        int slot = sh_slot[row];
        int pos  = sh_pos[row];
        const float* kp = k_cache + ((size_t)slot * KVH + kh) * DD;
        ka = *(const float2*)(kp + 2 * lane);
        kb = *(const float2*)(kp + 2 * lane + 64);
        const float* vp = v_cache + ((size_t)slot * KVH + kh) * DD;
        v = *(const float4*)(vp + 4 * lane);
        t = g_tab[pos * 32 + lane];
    };

    auto compute_row = [&](float2 Ka, float2 Kb, float4 V, float4 T) {
        // RoPE K (pairs (j, j+64)) from table
        float k0 = Ka.x * T.x - Kb.x * T.y;
        float k2 = Kb.x * T.x + Ka.x * T.y;
        float k1 = Ka.y * T.z - Kb.y * T.w;
        float k3 = Kb.y * T.z + Ka.y * T.w;

        float sc[GG];
#pragma unroll
        for (int g = 0; g < GG; g++) {
            float p = qr0[g] * k0 + qr1[g] * k1 + qr2[g] * k2 + qr3[g] * k3;
#pragma unroll
            for (int o = 16; o > 0; o >>= 1)
                p += __shfl_xor_sync(0xffffffffu, p, o);
            sc[g] = p * scale;
        }

#pragma unroll
        for (int g = 0; g < GG; g++) {
            float nm   = fmaxf(m[g], sc[g]);
            float corr = __expf(m[g] - nm);   // exp(-inf - x) = 0 on first hit
            float p    = __expf(sc[g] - nm);
            m[g] = nm;
            l[g] = l[g] * corr + p;
            acc[g][0] = acc[g][0] * corr + p * V.x;
            acc[g][1] = acc[g][1] * corr + p * V.y;
            acc[g][2] = acc[g][2] * corr + p * V.z;
            acc[g][3] = acc[g][3] * corr + p * V.w;
        }
    };

    int i = warp;
    if (i < n_rows)         load_row(i,         kaA, kbA, vA, tA);
    if (i + NWARP < n_rows) load_row(i + NWARP, kaB, kbB, vB, tB);

    while (i < n_rows) {
        // compute bufA (row i); prefetch row i+2*NWARP into bufA
        {
            float2 Ka = kaA, Kb = kbA; float4 V = vA, T = tA;
            if (i + 2 * NWARP < n_rows)
                load_row(i + 2 * NWARP, kaA, kbA, vA, tA);
            compute_row(Ka, Kb, V, T);
        }
        i += NWARP;
        if (i >= n_rows) break;

        // compute bufB (row i); prefetch row i+2*NWARP into bufB
        {
            float2 Ka = kaB, Kb = kbB; float4 V = vB, T = tB;
            if (i + 2 * NWARP < n_rows)
                load_row(i + 2 * NWARP, kaB, kbB, vB, tB);
            compute_row(Ka, Kb, V, T);
        }
        i += NWARP;
    }

    // Stash per-warp partials
#pragma unroll
    for (int g = 0; g < GG; g++) {
        if (lane == 0) {
            sm_m[warp][g] = m[g];
            sm_l[warp][g] = l[g];
        }
        sm_acc[warp][g][4 * lane + 0] = acc[g][0];
        sm_acc[warp][g][4 * lane + 1] = acc[g][1];
        sm_acc[warp][g][4 * lane + 2] = acc[g][2];
        sm_acc[warp][g][4 * lane + 3] = acc[g][3];
    }
    __syncthreads();

    // Warps 0..3 combine the 8 warp-partials for head g = warp
    if (warp < GG) {
        const int g = warp;
        float M = -INFINITY;
#pragma unroll
        for (int w = 0; w < NWARP; w++) M = fmaxf(M, sm_m[w][g]);

        float L = 0.0f;
        float o0 = 0.0f, o1 = 0.0f, o2 = 0.0f, o3 = 0.0f;
        if (M > -INFINITY) {
#pragma unroll
            for (int w = 0; w < NWARP; w++) {
                float e = __expf(sm_m[w][g] - M);
                L  += sm_l[w][g] * e;
                o0 += sm_acc[w][g][4 * lane + 0] * e;
                o1 += sm_acc[w][g][4 * lane + 1] * e;
                o2 += sm_acc[w][g][4 * lane + 2] * e;
                o3 += sm_acc[w][g][4 * lane + 3] * e;
            }
        }
        const int idx = (((b * KVH + kh) * GG + g) * NSPLIT + split);
        if (lane == 0) {
            g_m[idx] = M;
            g_l[idx] = L;
        }
        float* op = g_part + (size_t)idx * DD;
        op[4 * lane + 0] = o0;
        op[4 * lane + 1] = o1;
        op[4 * lane + 2] = o2;
        op[4 * lane + 3] = o3;
    }
}

// ---------------------------------------------------------------------------
// Combine: one warp per (b,h); 16 batched LDG.128 per lane for high MLP.
__global__ __launch_bounds__(128)
void attn_combine_kernel(float* __restrict__ out)
{
    const int warp = threadIdx.x >> 5;
    const int lane = threadIdx.x & 31;
    const int bhg  = blockIdx.x * 4 + warp;   // == b*HH + h

    float mv = (lane < NSPLIT) ? g_m[bhg * NSPLIT + lane] : -INFINITY;
    float lv = (lane < NSPLIT) ? g_l[bhg * NSPLIT + lane] : 0.0f;

    float M = mv;
#pragma unroll
    for (int o = 16; o > 0; o >>= 1)
        M = fmaxf(M, __shfl_xor_sync(0xffffffffu, M, o));

    float e = (lane < NSPLIT) ? __expf(mv - M) : 0.0f;   // 0 for empty splits
    float L = lv * e;
#pragma unroll
    for (int o = 16; o > 0; o >>= 1)
        L += __shfl_xor_sync(0xffffffffu, L, o);

    float o0 = 0.0f, o1 = 0.0f, o2 = 0.0f, o3 = 0.0f;
#pragma unroll
    for (int sp = 0; sp < NSPLIT; sp++) {
        float esp = __shfl_sync(0xffffffffu, e, sp);
        float4 p = *(const float4*)&g_part[((size_t)bhg * NSPLIT + sp) * DD + 4 * lane];
        o0 += p.x * esp;
        o1 += p.y * esp;
        o2 += p.z * esp;
        o3 += p.w * esp;
    }
    float inv = 1.0f / L;
    float4 r = make_float4(o0 * inv, o1 * inv, o2 * inv, o3 * inv);
    *(float4*)&out[(size_t)bhg * DD + 4 * lane] = r;
}

// ---------------------------------------------------------------------------
extern "C" void kernel_launch(void* const* d_in, const int* in_sizes, int n_in,
                              void* d_out, int out_size)
{
    const float* query     = (const float*)d_in[0];
    const float* k_cache   = (const float*)d_in[1];
    const float* v_cache   = (const float*)d_in[2];
    const int*   slots     = (const int*)d_in[3];
    const int*   positions = (const int*)d_in[4];
    const int*   ctx_lens  = (const int*)d_in[5];
    float* out = (float*)d_out;

    rope_table_kernel<<<POSMAX * 32 / 256, 256>>>();

    dim3 grid(NSPLIT, KVH, BB);
    attn_partial_kernel<<<grid, NTHREADS>>>(query, k_cache, v_cache,
                                            slots, positions, ctx_lens);

    attn_combine_kernel<<<BB * HH / 4, 128>>>(out);
}